// round 7
// baseline (speedup 1.0000x reference)
#include <cuda_runtime.h>
#include <cstdint>

#define N_NODES 100000
#define N_EDGES 1600000
#define DIM 64
#define HID 128
#define TILE_M 128
#define NT 782
#define TILES_PER_CTA 3
#define MLP_GRID 261

#if defined(__CUDA_ARCH_FEAT_SM103_ALL) || defined(__CUDA_ARCH_FEAT_SM100_ALL) || \
    defined(__CUDA_ARCH_FEAT_SM101_ALL)
#define HAS_TCGEN05 1
#else
#define HAS_TCGEN05 0
#endif

__device__ int g_idx_is64;
__device__ uint32_t g_w1t[DIM * HID];
__device__ uint32_t g_w2t[HID * DIM];
__device__ int g_off[N_NODES];     // counts -> exclusive prefix -> (after fill) inclusive end
__device__ int g_csr[N_EDGES];     // src ids grouped by dst

// ---------------------------------------------------------------------------
// helpers
// ---------------------------------------------------------------------------
__device__ __forceinline__ uint32_t smem_u32(const void* p) {
    uint32_t a;
    asm("{ .reg .u64 t; cvta.to.shared.u64 t, %1; cvt.u32.u64 %0, t; }" : "=r"(a) : "l"(p));
    return a;
}
__device__ __forceinline__ uint32_t elect_one() {
    uint32_t p;
    asm volatile("{ .reg .pred p; elect.sync _|p, 0xFFFFFFFF; selp.b32 %0, 1, 0, p; }" : "=r"(p));
    return p;
}
__device__ __forceinline__ uint32_t sw128(uint32_t b) { return b ^ ((b >> 3) & 0x70); }
__device__ __forceinline__ uint32_t cvt_tf32(float f) {
    uint32_t r;
    asm("cvt.rna.tf32.f32 %0, %1;" : "=r"(r) : "f"(f));
    return r;
}
__device__ __forceinline__ uint64_t make_desc(uint32_t addr) {
    return (uint64_t(2) << 61) | (uint64_t(1) << 46) | (uint64_t(64) << 32) |
           (uint64_t(1) << 16) | ((uint64_t)(addr >> 4) & 0x3FFF);
}
__device__ __forceinline__ unsigned int edge_dst(const void* ei_raw, int e) {
    if (g_idx_is64) return (unsigned int)((const long long*)ei_raw)[N_EDGES + e];
    return (unsigned int)((const int*)ei_raw)[N_EDGES + e];
}
__device__ __forceinline__ unsigned int edge_src(const void* ei_raw, int e) {
    if (g_idx_is64) return (unsigned int)((const long long*)ei_raw)[e];
    return (unsigned int)((const int*)ei_raw)[e];
}

#define MBAR_INIT(a, c) asm volatile("mbarrier.init.shared.b64 [%0], %1;" :: "r"(a), "r"(c) : "memory")
#define MBAR_INVAL(a)   asm volatile("mbarrier.inval.shared.b64 [%0];" :: "r"(a) : "memory")
#define MBAR_WAIT(a, ph) do {                                                     \
    uint32_t _m = (a), _p = (ph), _d;                                             \
    asm volatile("{ .reg .pred p; mbarrier.try_wait.parity.acquire.cta.shared::cta.b64 p, [%1], %2; selp.b32 %0,1,0,p; }" \
                 : "=r"(_d) : "r"(_m), "r"(_p) : "memory");                       \
    if (!_d) {                                                                    \
        asm volatile("{ .reg .pred P1; WL%=: mbarrier.try_wait.parity.acquire.cta.shared::cta.b64 P1, [%0], %1, 0x989680;" \
                     " @P1 bra.uni WD%=; bra.uni WL%=; WD%=: }"                   \
                     :: "r"(_m), "r"(_p) : "memory");                             \
    } } while (0)

#if HAS_TCGEN05
#define TC_ALLOC(sa, n)   asm volatile("tcgen05.alloc.cta_group::1.sync.aligned.shared::cta.b32 [%0], %1;" :: "r"(sa), "r"(n) : "memory")
#define TC_DEALLOC(t, n)  asm volatile("tcgen05.dealloc.cta_group::1.sync.aligned.b32 %0, %1;" :: "r"(t), "r"(n))
#define TC_RELINQ()       asm volatile("tcgen05.relinquish_alloc_permit.cta_group::1.sync.aligned;")
#define TC_COMMIT(mb)     asm volatile("tcgen05.commit.cta_group::1.mbarrier::arrive::one.shared::cluster.b64 [%0];" :: "r"(mb) : "memory")
#define TC_WAIT_LD()      asm volatile("tcgen05.wait::ld.sync.aligned;" ::: "memory")
#define TC_WAIT_ST()      asm volatile("tcgen05.wait::st.sync.aligned;" ::: "memory")
#define TC_FENCE_BEFORE() asm volatile("tcgen05.fence::before_thread_sync;" ::: "memory")
#define TC_FENCE_AFTER()  asm volatile("tcgen05.fence::after_thread_sync;" ::: "memory")
#define FENCE_ASYNC()     asm volatile("fence.proxy.async.shared::cta;" ::: "memory")

#define LDTM_X32(r, a)                                                              \
    asm volatile("tcgen05.ld.sync.aligned.32x32b.x32.b32 "                          \
        "{%0,%1,%2,%3,%4,%5,%6,%7,%8,%9,%10,%11,%12,%13,%14,%15,"                   \
        "%16,%17,%18,%19,%20,%21,%22,%23,%24,%25,%26,%27,%28,%29,%30,%31}, [%32];"  \
        : "=r"((r)[0]),"=r"((r)[1]),"=r"((r)[2]),"=r"((r)[3]),"=r"((r)[4]),"=r"((r)[5]),"=r"((r)[6]),"=r"((r)[7]), \
          "=r"((r)[8]),"=r"((r)[9]),"=r"((r)[10]),"=r"((r)[11]),"=r"((r)[12]),"=r"((r)[13]),"=r"((r)[14]),"=r"((r)[15]), \
          "=r"((r)[16]),"=r"((r)[17]),"=r"((r)[18]),"=r"((r)[19]),"=r"((r)[20]),"=r"((r)[21]),"=r"((r)[22]),"=r"((r)[23]), \
          "=r"((r)[24]),"=r"((r)[25]),"=r"((r)[26]),"=r"((r)[27]),"=r"((r)[28]),"=r"((r)[29]),"=r"((r)[30]),"=r"((r)[31]) \
        : "r"(a))

#define STTM_X32(a, r)                                                              \
    asm volatile("tcgen05.st.sync.aligned.32x32b.x32.b32 [%0], "                    \
        "{%1,%2,%3,%4,%5,%6,%7,%8,%9,%10,%11,%12,%13,%14,%15,%16,"                  \
        "%17,%18,%19,%20,%21,%22,%23,%24,%25,%26,%27,%28,%29,%30,%31,%32};"         \
        :: "r"(a),                                                                  \
           "r"((r)[0]),"r"((r)[1]),"r"((r)[2]),"r"((r)[3]),"r"((r)[4]),"r"((r)[5]),"r"((r)[6]),"r"((r)[7]), \
           "r"((r)[8]),"r"((r)[9]),"r"((r)[10]),"r"((r)[11]),"r"((r)[12]),"r"((r)[13]),"r"((r)[14]),"r"((r)[15]), \
           "r"((r)[16]),"r"((r)[17]),"r"((r)[18]),"r"((r)[19]),"r"((r)[20]),"r"((r)[21]),"r"((r)[22]),"r"((r)[23]), \
           "r"((r)[24]),"r"((r)[25]),"r"((r)[26]),"r"((r)[27]),"r"((r)[28]),"r"((r)[29]),"r"((r)[30]),"r"((r)[31]) \
        : "memory")

__device__ __forceinline__ void mma_tf32_ss(uint32_t d, uint64_t a, uint64_t b,
                                            uint32_t idesc, bool acc) {
    uint32_t e = acc ? 1u : 0u;
    asm volatile("{ .reg .pred p; setp.ne.u32 p, %4, 0;"
                 " tcgen05.mma.cta_group::1.kind::tf32 [%0], %1, %2, %3, p; }"
                 :: "r"(d), "l"(a), "l"(b), "r"(idesc), "r"(e) : "memory");
}
__device__ __forceinline__ void mma_tf32_ts(uint32_t d, uint32_t a, uint64_t b,
                                            uint32_t idesc, bool acc) {
    uint32_t e = acc ? 1u : 0u;
    asm volatile("{ .reg .pred p; setp.ne.u32 p, %4, 0;"
                 " tcgen05.mma.cta_group::1.kind::tf32 [%0], [%1], %2, %3, p; }"
                 :: "r"(d), "r"(a), "l"(b), "r"(idesc), "r"(e) : "memory");
}
#endif

// ---------------------------------------------------------------------------
// Kernel 0: detect int32 vs int64 edge index
// ---------------------------------------------------------------------------
__global__ void detect_kernel(const int* __restrict__ ei32) {
    int any = 0;
    #pragma unroll
    for (int i = 0; i < 64; i++) any |= ei32[2 * i + 1];
    g_idx_is64 = (any == 0) ? 1 : 0;
}

// ---------------------------------------------------------------------------
// Kernel 0b: precompute swizzled tf32 weight images
// ---------------------------------------------------------------------------
__global__ void prep_w_kernel(const float* __restrict__ W1,
                              const float* __restrict__ W2) {
    int idx = blockIdx.x * blockDim.x + threadIdx.x;
    if (idx >= DIM * HID) return;
    {
        int j = idx & 127, k = idx >> 7;
        uint32_t byte = ((j >> 3) + (k >> 5) * 16) * 1024 + (j & 7) * 128 + (k & 31) * 4;
        g_w1t[sw128(byte) >> 2] = cvt_tf32(W1[k * HID + j]);
    }
    {
        int d = idx & 63, k = idx >> 6;
        uint32_t byte = ((d >> 3) + (k >> 5) * 8) * 1024 + (d & 7) * 128 + (k & 31) * 4;
        g_w2t[sw128(byte) >> 2] = cvt_tf32(W2[k * DIM + d]);
    }
}

// ---------------------------------------------------------------------------
// CSR build: zero counts -> count -> scan -> fill
// ---------------------------------------------------------------------------
__global__ void zero_cnt_kernel() {
    int i = blockIdx.x * blockDim.x + threadIdx.x;
    if (i < N_NODES) g_off[i] = 0;
}

__global__ void count_kernel(const void* __restrict__ ei_raw) {
    int e = blockIdx.x * blockDim.x + threadIdx.x;
    if (e >= N_EDGES) return;
    unsigned int d = edge_dst(ei_raw, e);
    if (d < N_NODES) atomicAdd(&g_off[d], 1);
}

// single-block exclusive scan over g_off (100k ints), in place
__global__ __launch_bounds__(1024, 1) void scan_kernel() {
    __shared__ int ts[1024];
    const int CH = (N_NODES + 1023) / 1024;   // 98
    int t = threadIdx.x;
    int lo = t * CH, hi = min(lo + CH, N_NODES);

    int sum = 0;
    for (int i = lo; i < hi; i++) sum += g_off[i];
    ts[t] = sum;
    __syncthreads();
    // Kogge-Stone inclusive scan over 1024 partials
    #pragma unroll
    for (int off = 1; off < 1024; off <<= 1) {
        int v = (t >= off) ? ts[t - off] : 0;
        __syncthreads();
        ts[t] += v;
        __syncthreads();
    }
    int run = ts[t] - sum;   // exclusive prefix of this chunk
    for (int i = lo; i < hi; i++) {
        int v = g_off[i];
        g_off[i] = run;
        run += v;
    }
}

__global__ void fill_kernel(const void* __restrict__ ei_raw) {
    int e = blockIdx.x * blockDim.x + threadIdx.x;
    if (e >= N_EDGES) return;
    unsigned int d = edge_dst(ei_raw, e);
    unsigned int s = edge_src(ei_raw, e);
    if (d >= N_NODES || s >= N_NODES) return;
    int slot = atomicAdd(&g_off[d], 1);       // destructive: g_off[d] becomes end(d)
    g_csr[slot] = (int)s;
}

// ---------------------------------------------------------------------------
// Gather-aggregate: warp per node, lane = float2 slice of the 64-dim row.
// Writes self + neighbor sum (no atomics, fully overwrites out).
// After fill: start(n) = (n==0)?0:g_off[n-1], end(n) = g_off[n].
// ---------------------------------------------------------------------------
__global__ __launch_bounds__(256) void gather_kernel(const float* __restrict__ x,
                                                     float* __restrict__ out) {
    int w = (blockIdx.x * blockDim.x + threadIdx.x) >> 5;
    if (w >= N_NODES) return;
    int lane = threadIdx.x & 31;

    int end   = g_off[w];
    int start = (w == 0) ? 0 : g_off[w - 1];

    // self term
    float2 acc = __ldg((const float2*)(x + (size_t)w * DIM) + lane);

    for (int b = start; b < end; b += 32) {
        int nblk = min(32, end - b);
        int idx = (b + lane < end) ? __ldg(&g_csr[b + lane]) : 0;
        #pragma unroll 4
        for (int j = 0; j < nblk; j++) {
            int nb = __shfl_sync(0xffffffff, idx, j);
            float2 v = __ldg((const float2*)(x + (size_t)nb * DIM) + lane);
            acc.x += v.x;
            acc.y += v.y;
        }
    }
    *((float2*)(out + (size_t)w * DIM) + lane) = acc;
}

// ---------------------------------------------------------------------------
// MLP via tcgen05 (buf already holds self+neighbors)
// ---------------------------------------------------------------------------
#define SM_TMEM  0
#define SM_MBAR  8
#define SM_X     1024
#define SM_W1    (SM_X + 32768)
#define SM_W2    (SM_W1 + 32768)
#define SM_B1    (SM_W2 + 32768)
#define SM_B2    (SM_B1 + 512)
#define SM_TOTAL (SM_B2 + 512)

#define T_D1   0
#define T_A2   128
#define T_D2   0
#define T_COLS 256

#define IDESC1 ((1u << 4) | (2u << 7) | (2u << 10) | ((HID / 8) << 17) | ((TILE_M / 16) << 24))
#define IDESC2 ((1u << 4) | (2u << 7) | (2u << 10) | ((DIM / 8) << 17) | ((TILE_M / 16) << 24))

__global__ __launch_bounds__(256, 2)
void mlp_tc_kernel(float* __restrict__ buf,
                   const float* __restrict__ b1, const float* __restrict__ b2) {
#if HAS_TCGEN05
    extern __shared__ char smem[];
    uint32_t sb = smem_u32(smem);
    int tid = threadIdx.x;
    int wid = tid >> 5;
    int lid = tid & 31;
    int wg  = wid >> 2;
    uint32_t woff = (uint32_t)(wid & 3) << 21;

    if (wid == 0) {
        TC_ALLOC(sb + SM_TMEM, T_COLS);
        TC_RELINQ();
        if (elect_one()) MBAR_INIT(sb + SM_MBAR, 1);
    }
    __syncthreads();
    uint32_t tmem;
    asm volatile("ld.shared.b32 %0, [%1];" : "=r"(tmem) : "r"(sb + SM_TMEM));

    {
        const uint4* s1 = (const uint4*)g_w1t;
        const uint4* s2 = (const uint4*)g_w2t;
        uint4* d1 = (uint4*)(smem + SM_W1);
        uint4* d2 = (uint4*)(smem + SM_W2);
        for (int i = tid; i < DIM * HID / 4; i += 256) {
            d1[i] = __ldg(s1 + i);
            d2[i] = __ldg(s2 + i);
        }
    }
    if (tid < HID) ((float*)(smem + SM_B1))[tid] = b1[tid];
    if (tid < DIM) ((float*)(smem + SM_B2))[tid] = b2[tid];

    int ph = 0;
    #pragma unroll 1
    for (int t = 0; t < TILES_PER_CTA; t++) {
        int tile = blockIdx.x * TILES_PER_CTA + t;
        if (tile >= NT) break;
        int base = tile * TILE_M;

        __syncthreads();

        for (int i = tid; i < TILE_M * (DIM / 4); i += 256) {
            int row = i >> 4;
            int c4  = i & 15;
            int node = base + row;
            float4 s = make_float4(0.f, 0.f, 0.f, 0.f);
            if (node < N_NODES)
                s = __ldg(((const float4*)(buf + (size_t)node * DIM)) + c4);
            uint32_t byte = ((row >> 3) + (c4 >> 3) * 16) * 1024 + (row & 7) * 128 + (c4 & 7) * 16;
            *(uint4*)(smem + SM_X + sw128(byte)) =
                make_uint4(cvt_tf32(s.x), cvt_tf32(s.y), cvt_tf32(s.z), cvt_tf32(s.w));
        }
        FENCE_ASYNC();
        __syncthreads();

        if (wid == 0) {
            TC_FENCE_AFTER();
            if (elect_one()) {
                uint64_t ad = make_desc(sb + SM_X);
                uint64_t bd = make_desc(sb + SM_W1);
                #pragma unroll
                for (int s = 0; s < 8; s++) {
                    uint64_t off = (uint64_t)((s >> 2) * 1024 + (s & 3) * 2);
                    mma_tf32_ss(tmem + T_D1, ad + off, bd + off, IDESC1, s > 0);
                }
                TC_COMMIT(sb + SM_MBAR);
            }
        }
        MBAR_WAIT(sb + SM_MBAR, ph); ph ^= 1;
        TC_FENCE_AFTER();

        {
            const float* b1s = (const float*)(smem + SM_B1);
            #pragma unroll
            for (int blk = 0; blk < 2; blk++) {
                int c0 = wg * 64 + blk * 32;
                uint32_t r[32];
                LDTM_X32(r, tmem + woff + T_D1 + c0);
                TC_WAIT_LD();
                #pragma unroll
                for (int i = 0; i < 32; i++) {
                    float f = __uint_as_float(r[i]) + b1s[c0 + i];
                    r[i] = cvt_tf32(fmaxf(f, 0.f));
                }
                STTM_X32(tmem + woff + T_A2 + c0, r);
            }
            TC_WAIT_ST();
        }
        TC_FENCE_BEFORE();
        __syncthreads();

        if (wid == 0) {
            TC_FENCE_AFTER();
            if (elect_one()) {
                uint64_t bd = make_desc(sb + SM_W2);
                #pragma unroll
                for (int s = 0; s < 16; s++) {
                    uint64_t off = (uint64_t)((s >> 2) * 512 + (s & 3) * 2);
                    mma_tf32_ts(tmem + T_D2, tmem + T_A2 + s * 8, bd + off, IDESC2, s > 0);
                }
                TC_COMMIT(sb + SM_MBAR);
            }
        }
        MBAR_WAIT(sb + SM_MBAR, ph); ph ^= 1;
        TC_FENCE_AFTER();

        {
            const float* b2s = (const float*)(smem + SM_B2);
            int node = base + (wid & 3) * 32 + lid;
            int c0 = wg * 32;
            uint32_t r[32];
            LDTM_X32(r, tmem + woff + T_D2 + c0);
            TC_WAIT_LD();
            if (node < N_NODES) {
                float* op = buf + (size_t)node * DIM + c0;
                #pragma unroll
                for (int g = 0; g < 8; g++) {
                    float4 v;
                    v.x = __uint_as_float(r[4 * g + 0]) + b2s[c0 + 4 * g + 0];
                    v.y = __uint_as_float(r[4 * g + 1]) + b2s[c0 + 4 * g + 1];
                    v.z = __uint_as_float(r[4 * g + 2]) + b2s[c0 + 4 * g + 2];
                    v.w = __uint_as_float(r[4 * g + 3]) + b2s[c0 + 4 * g + 3];
                    *(float4*)(op + 4 * g) = v;
                }
            }
        }
        TC_FENCE_BEFORE();
    }

    __syncthreads();
    if (wid == 0) {
        if (elect_one()) MBAR_INVAL(sb + SM_MBAR);
        TC_DEALLOC(tmem, T_COLS);
    }
#endif
}

// ---------------------------------------------------------------------------
// Launch
// ---------------------------------------------------------------------------
extern "C" void kernel_launch(void* const* d_in, const int* in_sizes, int n_in,
                              void* d_out, int out_size) {
    const float* x  = (const float*)d_in[0];
    const void*  ei = d_in[1];
    const float* W1 = (const float*)d_in[2];
    const float* b1 = (const float*)d_in[3];
    const float* W2 = (const float*)d_in[4];
    const float* b2 = (const float*)d_in[5];
    float* out = (float*)d_out;

    cudaFuncSetAttribute(mlp_tc_kernel, cudaFuncAttributeMaxDynamicSharedMemorySize,
                         SM_TOTAL);

    detect_kernel<<<1, 1>>>((const int*)ei);
    prep_w_kernel<<<(DIM * HID + 255) / 256, 256>>>(W1, W2);

    // CSR build
    zero_cnt_kernel<<<(N_NODES + 255) / 256, 256>>>();
    count_kernel<<<(N_EDGES + 255) / 256, 256>>>(ei);
    scan_kernel<<<1, 1024>>>();
    fill_kernel<<<(N_EDGES + 255) / 256, 256>>>(ei);

    // aggregate (self + neighbors), no atomics
    gather_kernel<<<(N_NODES * 32 + 255) / 256, 256>>>(x, out);

    // MLP in place
    mlp_tc_kernel<<<MLP_GRID, 256, SM_TOTAL>>>(out, b1, b2);
}